// round 1
// baseline (speedup 1.0000x reference)
#include <cuda_runtime.h>
#include <math.h>
#include <math_constants.h>

// ---------------------------------------------------------------------------
// GraphResidualBlock: out = x + g(A_softmax @ x)  elementwise-restructured.
//
// Key identities:
//   softmax rows sum to 1  =>  mix(fc1(x)) = W1*s_m + b1,  s_m = (A@x)_m
//   g(s) = b2 + sum_h W2[h]*relu(W1[h]*s + b1[h])  is piecewise-linear in s
//          with 32 knots  t_h = -b1[h]/W1[h].
// Prep kernel (1 warp) builds sorted knots + 33 interval (alpha,beta) pairs.
// Main kernel: per row, 6x6 matvec for s, then 6-step branchless lower_bound
// and one FMA per output element.
// ---------------------------------------------------------------------------

__device__ float  g_A[36];      // softmax(A_param) row-major 6x6
__device__ float  g_knots[64];  // sorted knots, padded with +INF to 64
__device__ float2 g_ab[33];     // (alpha, beta) per interval, index = #knots < s

__global__ void prep_kernel(const float* __restrict__ A_param,
                            const float* __restrict__ W1,
                            const float* __restrict__ b1,
                            const float* __restrict__ W2,
                            const float* __restrict__ b2) {
    const int tid = threadIdx.x;  // 0..31

    // --- softmax rows of A_param (threads 0..5, one row each) ---
    if (tid < 6) {
        float v[6];
        float mx = -CUDART_INF_F;
        #pragma unroll
        for (int n = 0; n < 6; n++) { v[n] = A_param[tid * 6 + n]; mx = fmaxf(mx, v[n]); }
        float sum = 0.f;
        #pragma unroll
        for (int n = 0; n < 6; n++) { v[n] = expf(v[n] - mx); sum += v[n]; }
        const float inv = 1.0f / sum;
        #pragma unroll
        for (int n = 0; n < 6; n++) g_A[tid * 6 + n] = v[n] * inv;
    }

    // --- per-hidden-unit knot + slope/intercept deltas ---
    const float w1 = W1[tid];
    const float bb = b1[tid];
    const float w2 = W2[tid];

    float t, da, db;
    float base_a = 0.f, base_b = 0.f;  // g(s) = base_a*s + base_b as s -> -inf
    if (w1 > 0.f) {
        t = -bb / w1;            // activates (adds) when s crosses t upward
        da =  w2 * w1;  db =  w2 * bb;
    } else if (w1 < 0.f) {
        t = -bb / w1;            // deactivates (subtracts) when s crosses t upward
        da = -(w2 * w1); db = -(w2 * bb);
        base_a = w2 * w1; base_b = w2 * bb;   // active at -inf
    } else {
        t = CUDART_INF_F;        // constant term
        da = 0.f; db = 0.f;
        base_b = w2 * fmaxf(bb, 0.f);
    }

    // warp-reduce base_a/base_b
    #pragma unroll
    for (int o = 16; o; o >>= 1) {
        base_a += __shfl_xor_sync(0xFFFFFFFFu, base_a, o);
        base_b += __shfl_xor_sync(0xFFFFFFFFu, base_b, o);
    }

    // --- rank-sort the 32 knots ---
    __shared__ float st[32], ssa[32], ssb[32], sk[32];
    st[tid] = t;
    __syncwarp();
    int rank = 0;
    #pragma unroll
    for (int j = 0; j < 32; j++) {
        const float tj = st[j];
        rank += (tj < t) || (tj == t && j < tid);
    }
    __syncwarp();
    sk[rank]  = t;
    ssa[rank] = da;
    ssb[rank] = db;
    __syncwarp();

    // --- inclusive scan of sorted deltas (warp shuffle) ---
    float ia = ssa[tid], ib = ssb[tid];
    #pragma unroll
    for (int o = 1; o < 32; o <<= 1) {
        const float pa = __shfl_up_sync(0xFFFFFFFFu, ia, o);
        const float pb = __shfl_up_sync(0xFFFFFFFFu, ib, o);
        if (tid >= o) { ia += pa; ib += pb; }
    }

    const float b2v = b2[0];
    g_ab[tid + 1] = make_float2(base_a + ia, base_b + b2v + ib);
    if (tid == 0) g_ab[0] = make_float2(base_a, base_b + b2v);

    g_knots[tid]      = sk[tid];
    g_knots[tid + 32] = CUDART_INF_F;   // pad for pow2 branchless lower_bound
}

// ---------------------------------------------------------------------------
// Main kernel: 2 rows (12 floats = 3 x float4) per thread, fully coalesced.
// ---------------------------------------------------------------------------
#define TPB 256

__global__ __launch_bounds__(TPB) void main_kernel(const float4* __restrict__ x,
                                                   float4* __restrict__ out) {
    __shared__ float  sA[36];
    __shared__ float  sK[64];
    __shared__ float2 sAB[33];

    const int tid = threadIdx.x;
    if (tid < 36)                 sA[tid]        = g_A[tid];
    if (tid >= 64 && tid < 128)   sK[tid - 64]   = g_knots[tid - 64];
    if (tid >= 128 && tid < 161)  sAB[tid - 128] = g_ab[tid - 128];
    __syncthreads();

    const unsigned i = blockIdx.x * TPB + tid;   // thread handles rows 2i, 2i+1

    const float4 v0 = x[3u * i + 0u];
    const float4 v1 = x[3u * i + 1u];
    const float4 v2 = x[3u * i + 2u];

    float xs[12] = { v0.x, v0.y, v0.z, v0.w, v1.x, v1.y,
                     v1.z, v1.w, v2.x, v2.y, v2.z, v2.w };
    float res[12];

    #pragma unroll
    for (int r = 0; r < 2; r++) {
        #pragma unroll
        for (int m = 0; m < 6; m++) {
            float s = 0.f;
            #pragma unroll
            for (int n = 0; n < 6; n++)
                s = fmaf(sA[m * 6 + n], xs[6 * r + n], s);

            // branchless lower_bound over 64-entry padded sorted knot table
            int lo = 0;
            #pragma unroll
            for (int step = 32; step; step >>= 1)
                lo += (sK[lo + step - 1] < s) ? step : 0;

            const float2 ab = sAB[lo];
            res[6 * r + m] = xs[6 * r + m] + fmaf(ab.x, s, ab.y);
        }
    }

    out[3u * i + 0u] = make_float4(res[0], res[1], res[2],  res[3]);
    out[3u * i + 1u] = make_float4(res[4], res[5], res[6],  res[7]);
    out[3u * i + 2u] = make_float4(res[8], res[9], res[10], res[11]);
}

extern "C" void kernel_launch(void* const* d_in, const int* in_sizes, int n_in,
                              void* d_out, int out_size) {
    const float* x       = (const float*)d_in[0];
    const float* A_param = (const float*)d_in[1];
    const float* W1      = (const float*)d_in[2];
    const float* b1      = (const float*)d_in[3];
    const float* W2      = (const float*)d_in[4];
    const float* b2      = (const float*)d_in[5];
    float* out = (float*)d_out;

    prep_kernel<<<1, 32>>>(A_param, W1, b1, W2, b2);

    // B = 1048576 rows, 2 rows per thread -> 524288 threads -> 2048 blocks
    const int threads_total = 1048576 / 2;
    main_kernel<<<threads_total / TPB, TPB>>>((const float4*)x, (float4*)out);
}

// round 2
// speedup vs baseline: 1.1124x; 1.1124x over previous
#include <cuda_runtime.h>
#include <math.h>
#include <math_constants.h>

// ---------------------------------------------------------------------------
// GraphResidualBlock: out = x + g((softmax(A) @ x))  fully fused.
//
// Identities:
//   softmax rows sum to 1  =>  mixing commutes with the fc1 affine:
//     (A @ fc1(x))[m] = W1 * s_m + b1,  with scalar s_m = (A @ x)[m]
//   g(s) = b2 + sum_h W2[h]*relu(W1[h]*s + b1[h])  is piecewise-linear:
//     32 sorted knots t_h, 33 intervals with coefficients (alpha, beta).
//
// Single fused kernel: warp 0 of every block rebuilds the tiny tables
// (softmax(A)^T, sorted knots, prefix-scanned interval coefs) in shared,
// then all threads evaluate. Binary search levels 0-2 are register-resident
// (warp-uniform), only 3 deep levels + the (alpha,beta) fetch touch shared.
// ---------------------------------------------------------------------------

#define TPB 256

__global__ __launch_bounds__(TPB) void fused_kernel(
    const float4* __restrict__ x,
    float4* __restrict__ out,
    const float* __restrict__ A_param,
    const float* __restrict__ W1,
    const float* __restrict__ b1,
    const float* __restrict__ W2,
    const float* __restrict__ b2)
{
    __shared__ float  sAT[36];   // sAT[n*6 + m] = softmax(A)[m][n]  (column-major)
    __shared__ float  sK[64];    // sorted knots, padded with +INF
    __shared__ float2 sAB[33];   // (alpha, beta) per interval
    __shared__ float  st[32], ssa[32], ssb[32];  // prep scratch

    const int tid = threadIdx.x;

    // ---------------- per-block prep (warp 0 only, ~500 cyc) ----------------
    if (tid < 32) {
        // softmax rows of A_param (threads 0..5, one row each), store transposed
        if (tid < 6) {
            float v[6];
            float mx = -CUDART_INF_F;
            #pragma unroll
            for (int n = 0; n < 6; n++) { v[n] = A_param[tid * 6 + n]; mx = fmaxf(mx, v[n]); }
            float sum = 0.f;
            #pragma unroll
            for (int n = 0; n < 6; n++) { v[n] = expf(v[n] - mx); sum += v[n]; }
            const float inv = 1.0f / sum;
            #pragma unroll
            for (int n = 0; n < 6; n++) sAT[n * 6 + tid] = v[n] * inv;
        }

        // per-hidden-unit knot + slope/intercept deltas
        const float w1 = W1[tid];
        const float bb = b1[tid];
        const float w2 = W2[tid];

        float t, da, db;
        float base_a = 0.f, base_b = 0.f;   // g(s) as s -> -inf
        if (w1 > 0.f) {
            t = -bb / w1;  da =  w2 * w1;  db =  w2 * bb;
        } else if (w1 < 0.f) {
            t = -bb / w1;  da = -(w2 * w1); db = -(w2 * bb);
            base_a = w2 * w1; base_b = w2 * bb;
        } else {
            t = CUDART_INF_F; da = 0.f; db = 0.f;
            base_b = w2 * fmaxf(bb, 0.f);
        }

        #pragma unroll
        for (int o = 16; o; o >>= 1) {
            base_a += __shfl_xor_sync(0xFFFFFFFFu, base_a, o);
            base_b += __shfl_xor_sync(0xFFFFFFFFu, base_b, o);
        }

        // rank-sort the 32 knots
        st[tid] = t;
        __syncwarp();
        int rank = 0;
        #pragma unroll
        for (int j = 0; j < 32; j++) {
            const float tj = st[j];
            rank += (tj < t) || (tj == t && j < tid);
        }
        __syncwarp();
        sK[rank]  = t;
        ssa[rank] = da;
        ssb[rank] = db;
        sK[tid + 32] = CUDART_INF_F;
        __syncwarp();

        // inclusive scan of sorted deltas
        float ia = ssa[tid], ib = ssb[tid];
        #pragma unroll
        for (int o = 1; o < 32; o <<= 1) {
            const float pa = __shfl_up_sync(0xFFFFFFFFu, ia, o);
            const float pb = __shfl_up_sync(0xFFFFFFFFu, ib, o);
            if (tid >= o) { ia += pa; ib += pb; }
        }

        const float b2v = b2[0];
        sAB[tid + 1] = make_float2(base_a + ia, base_b + b2v + ib);
        if (tid == 0) sAB[0] = make_float2(base_a, base_b + b2v);
    }
    __syncthreads();

    // register-resident top 3 levels of the knot tree (warp-uniform values)
    const float k31 = sK[31];
    const float k15 = sK[15], k47 = sK[47];
    const float k7  = sK[7],  k23 = sK[23], k39 = sK[39], k55 = sK[55];

    // --------------------------- main evaluation ----------------------------
    const unsigned i = blockIdx.x * TPB + tid;   // handles rows 2i, 2i+1

    const float4 v0 = x[3u * i + 0u];
    const float4 v1 = x[3u * i + 1u];
    const float4 v2 = x[3u * i + 2u];

    float xs[12] = { v0.x, v0.y, v0.z, v0.w, v1.x, v1.y,
                     v1.z, v1.w, v2.x, v2.y, v2.z, v2.w };

    // s[m] (row0), s[6+m] (row1): stream A^T columns via float2 broadcasts
    float s[12];
    #pragma unroll
    for (int m = 0; m < 12; m++) s[m] = 0.f;

    #pragma unroll
    for (int n = 0; n < 6; n++) {
        const float2* ap = (const float2*)(sAT + n * 6);   // 24n bytes: 8-aligned
        const float2 a01 = ap[0], a23 = ap[1], a45 = ap[2];
        const float x0 = xs[n], x1 = xs[6 + n];
        s[0]  = fmaf(a01.x, x0, s[0]);   s[6]  = fmaf(a01.x, x1, s[6]);
        s[1]  = fmaf(a01.y, x0, s[1]);   s[7]  = fmaf(a01.y, x1, s[7]);
        s[2]  = fmaf(a23.x, x0, s[2]);   s[8]  = fmaf(a23.x, x1, s[8]);
        s[3]  = fmaf(a23.y, x0, s[3]);   s[9]  = fmaf(a23.y, x1, s[9]);
        s[4]  = fmaf(a45.x, x0, s[4]);   s[10] = fmaf(a45.x, x1, s[10]);
        s[5]  = fmaf(a45.y, x0, s[5]);   s[11] = fmaf(a45.y, x1, s[11]);
    }

    float res[12];
    #pragma unroll
    for (int e = 0; e < 12; e++) {
        const float sv = s[e];

        // lower_bound: levels 0-2 in registers, levels 3-5 in shared
        int lo = (k31 < sv) ? 32 : 0;
        const float kl1 = lo ? k47 : k15;
        lo += (kl1 < sv) ? 16 : 0;
        const float ka = (lo & 32) ? k39 : k7;
        const float kb = (lo & 32) ? k55 : k23;
        const float kl2 = (lo & 16) ? kb : ka;
        lo += (kl2 < sv) ? 8 : 0;
        lo += (sK[lo + 3] < sv) ? 4 : 0;
        lo += (sK[lo + 1] < sv) ? 2 : 0;
        lo += (sK[lo]     < sv) ? 1 : 0;

        const float2 ab = sAB[lo];
        res[e] = xs[e] + fmaf(ab.x, sv, ab.y);
    }

    out[3u * i + 0u] = make_float4(res[0], res[1], res[2],  res[3]);
    out[3u * i + 1u] = make_float4(res[4], res[5], res[6],  res[7]);
    out[3u * i + 2u] = make_float4(res[8], res[9], res[10], res[11]);
}

extern "C" void kernel_launch(void* const* d_in, const int* in_sizes, int n_in,
                              void* d_out, int out_size) {
    const float* x       = (const float*)d_in[0];
    const float* A_param = (const float*)d_in[1];
    const float* W1      = (const float*)d_in[2];
    const float* b1      = (const float*)d_in[3];
    const float* W2      = (const float*)d_in[4];
    const float* b2      = (const float*)d_in[5];
    float* out = (float*)d_out;

    // B = 1048576 rows, 2 rows/thread -> 524288 threads -> 2048 blocks
    fused_kernel<<<(1048576 / 2) / TPB, TPB>>>(
        (const float4*)x, (float4*)out, A_param, W1, b1, W2, b2);
}